// round 16
// baseline (speedup 1.0000x reference)
#include <cuda_runtime.h>
#include <math.h>

// Problem constants
#define NB 64
#define CB 64
#define DB 64
#define TB 300
#define VB 25
#define EPSB 1e-5f
#define NTOT (NB*TB)          // 19200 rows
#define FEAT (VB*DB)          // 1600 features
#define LTOT (TB+VB)          // 325
#define Y_SIZE (NB*DB*TB*VB)  // 30720000

#define K7T 6                 // t-rows per k7 block
#define K7_BLOCKS (NB*(TB/K7T))   // 3200

// ---------------- scratch (device globals; no runtime allocation) ----------------
__device__ float g_xv[NB*CB*TB];        // 4.9 MB
__device__ float g_xt[NB*CB*VB];        // 0.4 MB
__device__ float g_part1[NB*CB*4];      // per-(n,c) partials (sv,svv,st,stt)
__device__ float g_xs[NB*DB*LTOT];      // 5.3 MB
__device__ float g_part2[320*DB*2];     // per-(n,kc) per-o partials
__device__ float g_scale[VB*CB];        // tanh(sigmoid(view))+1, [w][c]
__device__ float g_y0[(size_t)NTOT*FEAT];     // 123 MB : SHIFTED layout [n][dd][t][i]
__device__ float g_part3[(size_t)K7_BLOCKS*3200];  // 41 MB : per-block BN partials
__device__ float g_stats3[FEAT*2];      // y0 feature mean/rstd (pre-shift feature w*64+dd)

__device__ __forceinline__ float hswish(float x) {
    float c = fminf(fmaxf(x + 3.0f, 0.0f), 6.0f);
    return x * c * (1.0f / 6.0f);
}
__device__ __forceinline__ unsigned long long pk2(float lo, float hi) {
    unsigned long long r;
    asm("mov.b64 %0, {%1, %2};" : "=l"(r) : "f"(lo), "f"(hi));
    return r;
}
__device__ __forceinline__ void upk2(float& lo, float& hi, unsigned long long v) {
    asm("mov.b64 {%0, %1}, %2;" : "=f"(lo), "=f"(hi) : "l"(v));
}
__device__ __forceinline__ void fma2(unsigned long long& d, unsigned long long a, unsigned long long b) {
    asm("fma.rn.f32x2 %0, %1, %2, %0;" : "+l"(d) : "l"(a), "l"(b));
}

// ---------------- K1: per-(n,c) slice — xv (V-reduce) + xt (T-reduce) + partials ----
__global__ void k1(const float* __restrict__ x0, const float* __restrict__ Wv,
                   const float* __restrict__ bv, const float* __restrict__ Wt,
                   const float* __restrict__ bt)
{
    __shared__ float xs_[TB*VB];
    __shared__ float wt_[TB];
    __shared__ float wvc[VB];
    __shared__ float red[64];
    __shared__ float xta[VB];

    int nc = blockIdx.x;
    int c  = nc & 63;
    int tid = threadIdx.x;

    const float4* src4 = (const float4*)(x0 + (size_t)nc * (TB*VB));
    for (int i = tid; i < 1875; i += blockDim.x) ((float4*)xs_)[i] = src4[i];
    for (int i = tid; i < TB;   i += blockDim.x) wt_[i] = Wt[i];
    if (tid < VB) {
        int v = (tid - c) % VB; if (v < 0) v += VB;
        wvc[tid] = Wv[v];
    }
    float bvv = bv[0], btv = bt[0];
    __syncthreads();

    float s = 0.f, ss = 0.f;
    for (int t = tid; t < TB; t += blockDim.x) {
        float a = bvv;
        #pragma unroll
        for (int v = 0; v < VB; v++) a += wvc[v] * xs_[t*VB + v];
        g_xv[nc*TB + t] = a;
        s += a; ss += a*a;
    }
    #pragma unroll
    for (int o = 16; o; o >>= 1) {
        s  += __shfl_down_sync(0xffffffffu, s,  o);
        ss += __shfl_down_sync(0xffffffffu, ss, o);
    }
    if ((tid & 31) == 0) { red[tid>>5] = s; red[32 + (tid>>5)] = ss; }

    if (tid < 224) {
        int vp = tid >> 3, sl = tid & 7;
        float a = 0.f;
        if (vp < VB) {
            for (int t = sl; t < TB; t += 8) a += wt_[t] * xs_[t*VB + vp];
        }
        a += __shfl_down_sync(0xffffffffu, a, 4);
        a += __shfl_down_sync(0xffffffffu, a, 2);
        a += __shfl_down_sync(0xffffffffu, a, 1);
        if (sl == 0 && vp < VB) {
            a += btv;
            int v = (vp - c) % VB; if (v < 0) v += VB;
            g_xt[nc*VB + v] = a;
            xta[vp] = a;
        }
    }
    __syncthreads();
    if (tid == 0) {
        float S = 0.f, SS = 0.f;
        for (int w = 0; w < (int)(blockDim.x >> 5); w++) { S += red[w]; SS += red[32+w]; }
        g_part1[nc*4 + 0] = S; g_part1[nc*4 + 1] = SS;
        S = 0.f; SS = 0.f;
        for (int v = 0; v < VB; v++) { S += xta[v]; SS += xta[v]*xta[v]; }
        g_part1[nc*4 + 2] = S; g_part1[nc*4 + 3] = SS;
    }
}

// ---------------- K3: inline stats1 + Ws stage (grid n x 5 chunks), 4x4 tiles ----------------
__global__ void k3(const float* __restrict__ gv, const float* __restrict__ bev,
                   const float* __restrict__ gt, const float* __restrict__ bet,
                   const float* __restrict__ Ws, const float* __restrict__ bs)
{
    extern __shared__ float sm3[];
    float* sfs    = sm3;            // [64][68]
    float* wst    = sm3 + 64*68;    // [64*64] transposed Ws
    float* red_s  = wst + 4096;     // [17][64]
    float* red_ss = red_s + 17*64;  // [17][64]
    __shared__ float rbuf[9*4];
    __shared__ float st1[4];

    int b = blockIdx.x;
    int n = b / 5, kc = b % 5;
    int tid = threadIdx.x;

    {
        float a0=0.f, a1=0.f, a2=0.f, a3=0.f;
        for (int j = tid; j < NB*CB; j += blockDim.x) {
            a0 += g_part1[j*4+0]; a1 += g_part1[j*4+1];
            a2 += g_part1[j*4+2]; a3 += g_part1[j*4+3];
        }
        #pragma unroll
        for (int o = 16; o; o >>= 1) {
            a0 += __shfl_down_sync(0xffffffffu, a0, o);
            a1 += __shfl_down_sync(0xffffffffu, a1, o);
            a2 += __shfl_down_sync(0xffffffffu, a2, o);
            a3 += __shfl_down_sync(0xffffffffu, a3, o);
        }
        if ((tid & 31) == 0) {
            int w = tid >> 5;
            rbuf[w*4+0]=a0; rbuf[w*4+1]=a1; rbuf[w*4+2]=a2; rbuf[w*4+3]=a3;
        }
        __syncthreads();
        if (tid == 0) {
            float A0=0,A1=0,A2=0,A3=0;
            for (int w = 0; w < 9; w++) { A0+=rbuf[w*4]; A1+=rbuf[w*4+1]; A2+=rbuf[w*4+2]; A3+=rbuf[w*4+3]; }
            float cntv = (float)(NB*CB*TB), cntt = (float)(NB*CB*VB);
            float mv = A0/cntv, vv = A1/cntv - mv*mv;
            float mt = A2/cntt, vt = A3/cntt - mt*mt;
            st1[0] = mv; st1[1] = rsqrtf(vv + EPSB);
            st1[2] = mt; st1[3] = rsqrtf(vt + EPSB);
        }
        __syncthreads();
    }
    float mv = st1[0], rv = st1[1], mt = st1[2], rt = st1[3];
    float gvv = gv[0], bevv = bev[0], gtv = gt[0], betv = bet[0];

    for (int i = tid; i < 64*68; i += blockDim.x) {
        int cc = i / 68, ll = i % 68;
        float val = 0.f;
        if (ll < 65) {
            int p = cc*LTOT + kc*65 + ll;
            if (p < 1600) {
                int cs = p / 25, v = p % 25;
                float x = g_xt[(n*64 + cs)*25 + v];
                val = hswish(gtv * (x - mt) * rt + betv);
            } else {
                int q = p - 1600;
                int cs = q / 300, t = q % 300;
                float x = g_xv[(n*64 + cs)*300 + t];
                val = hswish(gvv * (x - mv) * rv + bevv);
            }
        }
        sfs[i] = val;
    }
    for (int i = tid; i < 4096; i += blockDim.x) {
        int o = i & 63, cc = i >> 6;
        wst[i] = Ws[o*64 + cc];
    }
    __syncthreads();

    if (tid < 272) {
        int og = tid & 15, kg = tid >> 4;
        int o0 = og * 4, kl0 = kg * 4;
        float acc[4][4];
        #pragma unroll
        for (int j = 0; j < 4; j++) {
            float bb = bs[o0 + j];
            #pragma unroll
            for (int i = 0; i < 4; i++) acc[j][i] = bb;
        }
        for (int cc = 0; cc < 64; cc++) {
            float4 a = *(const float4*)&wst[cc*64 + o0];
            float4 bq = *(const float4*)&sfs[cc*68 + kl0];
            acc[0][0] += a.x*bq.x; acc[0][1] += a.x*bq.y; acc[0][2] += a.x*bq.z; acc[0][3] += a.x*bq.w;
            acc[1][0] += a.y*bq.x; acc[1][1] += a.y*bq.y; acc[1][2] += a.y*bq.z; acc[1][3] += a.y*bq.w;
            acc[2][0] += a.z*bq.x; acc[2][1] += a.z*bq.y; acc[2][2] += a.z*bq.z; acc[2][3] += a.z*bq.w;
            acc[3][0] += a.w*bq.x; acc[3][1] += a.w*bq.y; acc[3][2] += a.w*bq.z; acc[3][3] += a.w*bq.w;
        }
        #pragma unroll
        for (int j = 0; j < 4; j++) {
            float s = 0.f, ssum = 0.f;
            #pragma unroll
            for (int i = 0; i < 4; i++) {
                int kl = kl0 + i;
                if (kl < 65) {
                    float v = acc[j][i];
                    g_xs[(n*64 + o0 + j)*LTOT + kc*65 + kl] = v;
                    s += v; ssum += v*v;
                }
            }
            red_s [kg*64 + o0 + j] = s;
            red_ss[kg*64 + o0 + j] = ssum;
        }
    }
    __syncthreads();
    if (tid < 64) {
        float S = 0.f, SS = 0.f;
        for (int kg = 0; kg < 17; kg++) { S += red_s[kg*64 + tid]; SS += red_ss[kg*64 + tid]; }
        g_part2[(b*64 + tid)*2 + 0] = S;
        g_part2[(b*64 + tid)*2 + 1] = SS;
    }
}

// ---------------- K56: fused stats2 + xbar column + squeeze outputs (block per l) ----
__global__ void k56(const float* __restrict__ gs, const float* __restrict__ bes,
                    const float* __restrict__ Wt2, const float* __restrict__ bt2,
                    const float* __restrict__ Wv2, const float* __restrict__ bv2,
                    float* __restrict__ out_xtime)
{
    __shared__ float w2t[4096];
    __shared__ float red_a[256], red_b[256];
    __shared__ float stats2_s[128];
    __shared__ float xbar_s[64];

    int l = blockIdx.x;
    int tid = threadIdx.x;

    const float* W2 = (l < TB) ? Wt2 : Wv2;
    for (int i = tid; i < 4096; i += blockDim.x) {
        int o = i >> 6, d = i & 63;
        w2t[d*64 + o] = W2[i];
    }

    {
        int o = tid & 63, sl = tid >> 6;
        float s = 0.f, ss = 0.f;
        for (int ch = sl; ch < 320; ch += 4) {
            s  += g_part2[(ch*64 + o)*2 + 0];
            ss += g_part2[(ch*64 + o)*2 + 1];
        }
        red_a[tid] = s; red_b[tid] = ss;
        __syncthreads();
        if (tid < 64) {
            float S  = red_a[tid] + red_a[64+tid] + red_a[128+tid] + red_a[192+tid];
            float SS = red_b[tid] + red_b[64+tid] + red_b[128+tid] + red_b[192+tid];
            float cnt = 64.f * (float)LTOT;
            float m = S/cnt, v = SS/cnt - m*m;
            stats2_s[tid*2 + 0] = m;
            stats2_s[tid*2 + 1] = rsqrtf(v + EPSB);
        }
        __syncthreads();
    }

    {
        int d = tid & 63, ns = tid >> 6;
        float m = stats2_s[d*2], r = stats2_s[d*2+1];
        float g = gs[d], bb = bes[d];
        float acc = 0.f;
        for (int n = ns; n < 64; n += 4)
            acc += hswish(g * (g_xs[(n*64 + d)*LTOT + l] - m) * r + bb);
        red_a[tid] = acc;
        __syncthreads();
        if (tid < 64)
            xbar_s[tid] = (red_a[tid] + red_a[64+tid] + red_a[128+tid] + red_a[192+tid]) * (1.0f/64.0f);
        __syncthreads();
    }

    if (tid < 64) {
        int o = tid;
        float acc = (l < TB) ? bt2[o] : bv2[o];
        #pragma unroll 8
        for (int d = 0; d < 64; d++) acc += w2t[d*64 + o] * xbar_s[d];
        float sg = 1.0f / (1.0f + expf(-acc));
        if (l < TB) out_xtime[o*TB + l] = sg;
        else        g_scale[(l - TB)*64 + o] = tanhf(sg) + 1.0f;
    }
}

// ---------------- K7: GEMM + inline BN partials + shifted-layout store ----------------
// 800 threads = 25 warps, 2 blocks/SM (occupancy!). warp w, lane ddg; 6t x 2dd via FFMA2.
#define XMP_CS 8        // 6 t used + 2 pad; 32B per c -> LDS.128 aligned
#define XMP_WS 516      // 64*8 + 4 pad
#define XMP_TOT (VB*XMP_WS)   // 12900 floats; also reused as 64x150 perm buffer (9600)
__global__ void __launch_bounds__(800, 2)
k7(const float* __restrict__ x0, const float* __restrict__ Lw,
   const float* __restrict__ Lb)
{
    extern __shared__ float sm7[];
    float* xmp = sm7;                 // 12900
    float* lws = sm7 + XMP_TOT;       // 4096, 16B-aligned (12900*4 % 16 == 0)
    float* ssc = lws + 4096;          // 25*65
    float* lbs = ssc + 1625;          // 64

    int b = blockIdx.x;
    int n = b / (TB/K7T);             // TB/K7T = 50
    int t0 = (b % (TB/K7T)) * K7T;
    int tid = threadIdx.x;

    for (int i = tid; i < 4096; i += 800) lws[i] = Lw[i];
    for (int i = tid; i < VB*CB; i += 800) {
        int w = i >> 6, c = i & 63;
        ssc[w*65 + c] = g_scale[i];
    }
    if (tid < 64) lbs[tid] = Lb[tid];
    __syncthreads();

    // build: exactly 2 (c,v) pairs per thread; strength-reduced t-loop (MLP 6)
    const float* xbase = x0 + ((size_t)(n*64) * 300 + t0) * 25;
    #pragma unroll
    for (int rep = 0; rep < 2; rep++) {
        int pr = rep*800 + tid;
        int c = pr / 25;
        int v = pr - c*25;
        int w = v - (c % 25); if (w < 0) w += 25;
        float sc = ssc[w*65 + c];
        const float* src = xbase + (size_t)c * 7500 + v;
        float* dst = xmp + w*XMP_WS + c*XMP_CS;
        #pragma unroll
        for (int t = 0; t < K7T; t++)
            dst[t] = src[t*25] * sc;
    }
    __syncthreads();

    int w   = tid >> 5;     // warp index == w, 0..24
    int ddg = tid & 31;
    int dd0 = ddg << 1;
    unsigned long long acc[3][2];

    {
        const unsigned long long* xq = (const unsigned long long*)(xmp + w*XMP_WS);
        {
            unsigned long long i0 = pk2(lbs[dd0],     lbs[dd0]);
            unsigned long long i1 = pk2(lbs[dd0 + 1], lbs[dd0 + 1]);
            #pragma unroll
            for (int tp = 0; tp < 3; tp++) { acc[tp][0] = i0; acc[tp][1] = i1; }
        }
        #pragma unroll 4
        for (int c = 0; c < 64; c++) {
            ulonglong2 A01 = *(const ulonglong2*)(xq + c*4);   // (t0,t1),(t2,t3)
            unsigned long long A2 = xq[c*4 + 2];               // (t4,t5)
            float2 bf = *(const float2*)&lws[(c << 6) + dd0];
            unsigned long long b0 = pk2(bf.x, bf.x);
            unsigned long long b1 = pk2(bf.y, bf.y);
            fma2(acc[0][0], A01.x, b0); fma2(acc[0][1], A01.x, b1);
            fma2(acc[1][0], A01.y, b0); fma2(acc[1][1], A01.y, b1);
            fma2(acc[2][0], A2,    b0); fma2(acc[2][1], A2,    b1);
        }
    }
    __syncthreads();   // all xmp reads done; reuse as permute buffer

    float* ysm = sm7;  // [64][150]: dd*150 + t*25 + i
    {
        int i_e = (w + dd0) % 25;          // dest i for feature dd0
        int i_o = (w + dd0 + 1) % 25;      // dest i for feature dd0+1
        float* ysm_e = ysm + dd0*150 + i_e;
        float* ysm_o = ysm + (dd0 + 1)*150 + i_o;
        float psum0 = 0.f, psum1 = 0.f, psq0 = 0.f, psq1 = 0.f;
        #pragma unroll
        for (int tp = 0; tp < 3; tp++) {
            float e0, o0, e1, o1;
            upk2(e0, o0, acc[tp][0]);      // (t=2tp, dd0), (t=2tp+1, dd0)
            upk2(e1, o1, acc[tp][1]);      // (t=2tp, dd0+1), (t=2tp+1, dd0+1)
            ysm_e[(2*tp)*25]     = e0;
            ysm_o[(2*tp)*25]     = e1;
            ysm_e[(2*tp + 1)*25] = o0;
            ysm_o[(2*tp + 1)*25] = o1;
            psum0 += e0 + o0; psq0 += e0*e0 + o0*o0;
            psum1 += e1 + o1; psq1 += e1*e1 + o1*o1;
        }
        *(float2*)&g_part3[(size_t)b*3200 + (w << 6) + dd0]        = make_float2(psum0, psum1);
        *(float2*)&g_part3[(size_t)b*3200 + 1600 + (w << 6) + dd0] = make_float2(psq0,  psq1);
    }
    __syncthreads();

    // coalesced float2 store: g_y0 layout [n][dd][t][i]; 4800 float2 = 6 per thread.
    size_t base = (size_t)n * 480000 + (size_t)t0 * 25;
    #pragma unroll
    for (int k = 0; k < 6; k++) {
        int idx2 = k*800 + tid;            // float2 index, 0..4799
        int dd = idx2 / 75;
        int r2 = idx2 - dd*75;
        *(float2*)&g_y0[base + (size_t)dd*7500 + 2*r2] =
            *(const float2*)&ysm[dd*150 + 2*r2];
    }
}

// ---------------- K8b: reduce BN partials -> per-feature stats ----------------
__global__ void k8b()
{
    __shared__ float red_s[256], red_ss[256];
    int f = blockIdx.x * 32 + (threadIdx.x & 31);
    int sl = threadIdx.x >> 5;
    float s = 0.f, ss = 0.f;
    for (int b = sl; b < K7_BLOCKS; b += 8) {
        s  += g_part3[(size_t)b*3200 + f];
        ss += g_part3[(size_t)b*3200 + 1600 + f];
    }
    red_s[threadIdx.x] = s; red_ss[threadIdx.x] = ss;
    __syncthreads();
    if (threadIdx.x < 32) {
        float S = 0.f, SS = 0.f;
        #pragma unroll
        for (int k = 0; k < 8; k++) { S += red_s[k*32 + threadIdx.x]; SS += red_ss[k*32 + threadIdx.x]; }
        int ff = blockIdx.x * 32 + threadIdx.x;
        float cnt = (float)NTOT;
        float m = S/cnt, v = SS/cnt - m*m;
        g_stats3[ff*2 + 0] = m;
        g_stats3[ff*2 + 1] = rsqrtf(v + EPSB);
    }
}

// ---------------- K9: pure streaming BN + residual + relu ----------------
// g_y0 is already in output layout [n][dd][t][i]; block = one (n,dd) row (7500 floats).
__global__ void k9(const float* __restrict__ x0, const float* __restrict__ gbn,
                   const float* __restrict__ bbn, float* __restrict__ out)
{
    __shared__ float A[25], Bc[25];
    int b = blockIdx.x;            // n*64 + dd
    int dd = b & 63;
    int tid = threadIdx.x;

    if (tid < 25) {
        int i = tid;
        int wsrc = i - (dd % 25); if (wsrc < 0) wsrc += 25;   // pre-shift w for (i,dd)
        int p = wsrc*64 + dd;      // stats feature (pre-shift)
        int q = i*64 + dd;         // gbn/bbn feature (post-shift)
        float m = g_stats3[p*2], r = g_stats3[p*2 + 1];
        float g = gbn[q];
        A[i]  = g * r;
        Bc[i] = bbn[q] - g * r * m;
    }
    __syncthreads();

    const float4* y4 = (const float4*)(g_y0 + (size_t)b * 7500);
    const float4* x4 = (const float4*)(x0   + (size_t)b * 7500);
    float4*       o4 = (float4*)(out        + (size_t)b * 7500);
    for (int p4 = tid; p4 < 1875; p4 += blockDim.x) {
        float4 y = y4[p4];
        float4 x = x4[p4];
        int i = (p4 << 2) % 25;
        float4 o;
        o.x = fmaxf(fmaf(A[i], y.x, Bc[i]) + x.x, 0.f); if (++i == 25) i = 0;
        o.y = fmaxf(fmaf(A[i], y.y, Bc[i]) + x.y, 0.f); if (++i == 25) i = 0;
        o.z = fmaxf(fmaf(A[i], y.z, Bc[i]) + x.z, 0.f); if (++i == 25) i = 0;
        o.w = fmaxf(fmaf(A[i], y.w, Bc[i]) + x.w, 0.f);
        o4[p4] = o;
    }
}

// ---------------- launcher (6 launches; slot 4 = k7 for ncu capture) ----------------
extern "C" void kernel_launch(void* const* d_in, const int* in_sizes, int n_in,
                              void* d_out, int out_size)
{
    const float* x0  = (const float*)d_in[0];
    const float* Wv  = (const float*)d_in[3];
    const float* bv  = (const float*)d_in[4];
    const float* gv  = (const float*)d_in[5];
    const float* bev = (const float*)d_in[6];
    const float* Wt  = (const float*)d_in[7];
    const float* bt  = (const float*)d_in[8];
    const float* gt  = (const float*)d_in[9];
    const float* bet = (const float*)d_in[10];
    const float* Ws  = (const float*)d_in[11];
    const float* bs  = (const float*)d_in[12];
    const float* gs  = (const float*)d_in[13];
    const float* bes = (const float*)d_in[14];
    const float* Wv2 = (const float*)d_in[15];
    const float* bv2 = (const float*)d_in[16];
    const float* Wt2 = (const float*)d_in[17];
    const float* bt2 = (const float*)d_in[18];
    const float* Lw  = (const float*)d_in[19];
    const float* Lb  = (const float*)d_in[20];
    const float* gbn = (const float*)d_in[21];
    const float* bbn = (const float*)d_in[22];
    float* out = (float*)d_out;

    static_assert((TB % K7T) == 0, "k7 t tiling");
    static_assert((XMP_TOT % 4) == 0, "xmp align");
    static_assert(XMP_CS * CB < XMP_WS, "xmp pad");
    static_assert(DB * 150 <= XMP_TOT, "perm buffer fits");
    static_assert(CB*VB == 2*800, "build pairs = 2/thread");

    const int smem3 = (64*68 + 4096 + 17*64*2) * 4;                 // 51200
    const int smem7 = (XMP_TOT + 4096 + 1625 + 64) * 4;             // 74740
    cudaFuncSetAttribute(k3, cudaFuncAttributeMaxDynamicSharedMemorySize, smem3);
    cudaFuncSetAttribute(k7, cudaFuncAttributeMaxDynamicSharedMemorySize, smem7);

    k1 <<<NB*CB, 256>>>(x0, Wv, bv, Wt, bt);
    k3 <<<NB*5, 288, smem3>>>(gv, bev, gt, bet, Ws, bs);
    k56<<<LTOT, 256>>>(gs, bes, Wt2, bt2, Wv2, bv2, out + Y_SIZE);
    k7 <<<K7_BLOCKS, 800, smem7>>>(x0, Lw, Lb);
    k8b<<<FEAT/32, 256>>>();
    k9 <<<NB*DB, 256>>>(x0, gbn, bbn, out);
}

// round 17
// speedup vs baseline: 1.1463x; 1.1463x over previous
#include <cuda_runtime.h>
#include <cuda_fp16.h>
#include <math.h>

// Problem constants
#define NB 64
#define CB 64
#define DB 64
#define TB 300
#define VB 25
#define EPSB 1e-5f
#define NTOT (NB*TB)          // 19200 rows
#define FEAT (VB*DB)          // 1600 features
#define LTOT (TB+VB)          // 325
#define Y_SIZE (NB*DB*TB*VB)  // 30720000

#define K7T 12                // t-rows per k7 block
#define K7_BLOCKS (NB*(TB/K7T))   // 1600

// ---------------- scratch (device globals; no runtime allocation) ----------------
__device__ float g_xv[NB*CB*TB];        // 4.9 MB
__device__ float g_xt[NB*CB*VB];        // 0.4 MB
__device__ float g_part1[NB*CB*4];      // per-(n,c) partials (sv,svv,st,stt)
__device__ float g_xs[NB*DB*LTOT];      // 5.3 MB
__device__ float g_part2[320*DB*2];     // per-(n,kc) per-o partials
__device__ float g_scale[VB*CB];        // tanh(sigmoid(view))+1, [w][c]
__device__ __half g_y0h[(size_t)NTOT*FEAT];   // 61.5 MB : SHIFTED layout [n][dd][t][i], fp16
__device__ float g_part3[K7_BLOCKS*3200];     // 20.5 MB : per-block BN partials (fp32)
__device__ float g_stats3[FEAT*2];      // y0 feature mean/rstd (pre-shift feature w*64+dd)

__device__ __forceinline__ float hswish(float x) {
    float c = fminf(fmaxf(x + 3.0f, 0.0f), 6.0f);
    return x * c * (1.0f / 6.0f);
}
__device__ __forceinline__ unsigned long long pk2(float lo, float hi) {
    unsigned long long r;
    asm("mov.b64 %0, {%1, %2};" : "=l"(r) : "f"(lo), "f"(hi));
    return r;
}
__device__ __forceinline__ void upk2(float& lo, float& hi, unsigned long long v) {
    asm("mov.b64 {%0, %1}, %2;" : "=f"(lo), "=f"(hi) : "l"(v));
}
__device__ __forceinline__ void fma2(unsigned long long& d, unsigned long long a, unsigned long long b) {
    asm("fma.rn.f32x2 %0, %1, %2, %0;" : "+l"(d) : "l"(a), "l"(b));
}

// ---------------- K1: per-(n,c) slice — xv (V-reduce) + xt (T-reduce) + partials ----
__global__ void k1(const float* __restrict__ x0, const float* __restrict__ Wv,
                   const float* __restrict__ bv, const float* __restrict__ Wt,
                   const float* __restrict__ bt)
{
    __shared__ float xs_[TB*VB];
    __shared__ float wt_[TB];
    __shared__ float wvc[VB];
    __shared__ float red[64];
    __shared__ float xta[VB];

    int nc = blockIdx.x;
    int c  = nc & 63;
    int tid = threadIdx.x;

    const float4* src4 = (const float4*)(x0 + (size_t)nc * (TB*VB));
    for (int i = tid; i < 1875; i += blockDim.x) ((float4*)xs_)[i] = src4[i];
    for (int i = tid; i < TB;   i += blockDim.x) wt_[i] = Wt[i];
    if (tid < VB) {
        int v = (tid - c) % VB; if (v < 0) v += VB;
        wvc[tid] = Wv[v];
    }
    float bvv = bv[0], btv = bt[0];
    __syncthreads();

    float s = 0.f, ss = 0.f;
    for (int t = tid; t < TB; t += blockDim.x) {
        float a = bvv;
        #pragma unroll
        for (int v = 0; v < VB; v++) a += wvc[v] * xs_[t*VB + v];
        g_xv[nc*TB + t] = a;
        s += a; ss += a*a;
    }
    #pragma unroll
    for (int o = 16; o; o >>= 1) {
        s  += __shfl_down_sync(0xffffffffu, s,  o);
        ss += __shfl_down_sync(0xffffffffu, ss, o);
    }
    if ((tid & 31) == 0) { red[tid>>5] = s; red[32 + (tid>>5)] = ss; }

    if (tid < 224) {
        int vp = tid >> 3, sl = tid & 7;
        float a = 0.f;
        if (vp < VB) {
            for (int t = sl; t < TB; t += 8) a += wt_[t] * xs_[t*VB + vp];
        }
        a += __shfl_down_sync(0xffffffffu, a, 4);
        a += __shfl_down_sync(0xffffffffu, a, 2);
        a += __shfl_down_sync(0xffffffffu, a, 1);
        if (sl == 0 && vp < VB) {
            a += btv;
            int v = (vp - c) % VB; if (v < 0) v += VB;
            g_xt[nc*VB + v] = a;
            xta[vp] = a;
        }
    }
    __syncthreads();
    if (tid == 0) {
        float S = 0.f, SS = 0.f;
        for (int w = 0; w < (int)(blockDim.x >> 5); w++) { S += red[w]; SS += red[32+w]; }
        g_part1[nc*4 + 0] = S; g_part1[nc*4 + 1] = SS;
        S = 0.f; SS = 0.f;
        for (int v = 0; v < VB; v++) { S += xta[v]; SS += xta[v]*xta[v]; }
        g_part1[nc*4 + 2] = S; g_part1[nc*4 + 3] = SS;
    }
}

// ---------------- K3: inline stats1 + Ws stage (grid n x 5 chunks), 4x4 tiles ----------------
__global__ void k3(const float* __restrict__ gv, const float* __restrict__ bev,
                   const float* __restrict__ gt, const float* __restrict__ bet,
                   const float* __restrict__ Ws, const float* __restrict__ bs)
{
    extern __shared__ float sm3[];
    float* sfs    = sm3;            // [64][68]
    float* wst    = sm3 + 64*68;    // [64*64] transposed Ws
    float* red_s  = wst + 4096;     // [17][64]
    float* red_ss = red_s + 17*64;  // [17][64]
    __shared__ float rbuf[9*4];
    __shared__ float st1[4];

    int b = blockIdx.x;
    int n = b / 5, kc = b % 5;
    int tid = threadIdx.x;

    {
        float a0=0.f, a1=0.f, a2=0.f, a3=0.f;
        for (int j = tid; j < NB*CB; j += blockDim.x) {
            a0 += g_part1[j*4+0]; a1 += g_part1[j*4+1];
            a2 += g_part1[j*4+2]; a3 += g_part1[j*4+3];
        }
        #pragma unroll
        for (int o = 16; o; o >>= 1) {
            a0 += __shfl_down_sync(0xffffffffu, a0, o);
            a1 += __shfl_down_sync(0xffffffffu, a1, o);
            a2 += __shfl_down_sync(0xffffffffu, a2, o);
            a3 += __shfl_down_sync(0xffffffffu, a3, o);
        }
        if ((tid & 31) == 0) {
            int w = tid >> 5;
            rbuf[w*4+0]=a0; rbuf[w*4+1]=a1; rbuf[w*4+2]=a2; rbuf[w*4+3]=a3;
        }
        __syncthreads();
        if (tid == 0) {
            float A0=0,A1=0,A2=0,A3=0;
            for (int w = 0; w < 9; w++) { A0+=rbuf[w*4]; A1+=rbuf[w*4+1]; A2+=rbuf[w*4+2]; A3+=rbuf[w*4+3]; }
            float cntv = (float)(NB*CB*TB), cntt = (float)(NB*CB*VB);
            float mv = A0/cntv, vv = A1/cntv - mv*mv;
            float mt = A2/cntt, vt = A3/cntt - mt*mt;
            st1[0] = mv; st1[1] = rsqrtf(vv + EPSB);
            st1[2] = mt; st1[3] = rsqrtf(vt + EPSB);
        }
        __syncthreads();
    }
    float mv = st1[0], rv = st1[1], mt = st1[2], rt = st1[3];
    float gvv = gv[0], bevv = bev[0], gtv = gt[0], betv = bet[0];

    for (int i = tid; i < 64*68; i += blockDim.x) {
        int cc = i / 68, ll = i % 68;
        float val = 0.f;
        if (ll < 65) {
            int p = cc*LTOT + kc*65 + ll;
            if (p < 1600) {
                int cs = p / 25, v = p % 25;
                float x = g_xt[(n*64 + cs)*25 + v];
                val = hswish(gtv * (x - mt) * rt + betv);
            } else {
                int q = p - 1600;
                int cs = q / 300, t = q % 300;
                float x = g_xv[(n*64 + cs)*300 + t];
                val = hswish(gvv * (x - mv) * rv + bevv);
            }
        }
        sfs[i] = val;
    }
    for (int i = tid; i < 4096; i += blockDim.x) {
        int o = i & 63, cc = i >> 6;
        wst[i] = Ws[o*64 + cc];
    }
    __syncthreads();

    if (tid < 272) {
        int og = tid & 15, kg = tid >> 4;
        int o0 = og * 4, kl0 = kg * 4;
        float acc[4][4];
        #pragma unroll
        for (int j = 0; j < 4; j++) {
            float bb = bs[o0 + j];
            #pragma unroll
            for (int i = 0; i < 4; i++) acc[j][i] = bb;
        }
        for (int cc = 0; cc < 64; cc++) {
            float4 a = *(const float4*)&wst[cc*64 + o0];
            float4 bq = *(const float4*)&sfs[cc*68 + kl0];
            acc[0][0] += a.x*bq.x; acc[0][1] += a.x*bq.y; acc[0][2] += a.x*bq.z; acc[0][3] += a.x*bq.w;
            acc[1][0] += a.y*bq.x; acc[1][1] += a.y*bq.y; acc[1][2] += a.y*bq.z; acc[1][3] += a.y*bq.w;
            acc[2][0] += a.z*bq.x; acc[2][1] += a.z*bq.y; acc[2][2] += a.z*bq.z; acc[2][3] += a.z*bq.w;
            acc[3][0] += a.w*bq.x; acc[3][1] += a.w*bq.y; acc[3][2] += a.w*bq.z; acc[3][3] += a.w*bq.w;
        }
        #pragma unroll
        for (int j = 0; j < 4; j++) {
            float s = 0.f, ssum = 0.f;
            #pragma unroll
            for (int i = 0; i < 4; i++) {
                int kl = kl0 + i;
                if (kl < 65) {
                    float v = acc[j][i];
                    g_xs[(n*64 + o0 + j)*LTOT + kc*65 + kl] = v;
                    s += v; ssum += v*v;
                }
            }
            red_s [kg*64 + o0 + j] = s;
            red_ss[kg*64 + o0 + j] = ssum;
        }
    }
    __syncthreads();
    if (tid < 64) {
        float S = 0.f, SS = 0.f;
        for (int kg = 0; kg < 17; kg++) { S += red_s[kg*64 + tid]; SS += red_ss[kg*64 + tid]; }
        g_part2[(b*64 + tid)*2 + 0] = S;
        g_part2[(b*64 + tid)*2 + 1] = SS;
    }
}

// ---------------- K56: fused stats2 + xbar column + squeeze outputs (block per l) ----
__global__ void k56(const float* __restrict__ gs, const float* __restrict__ bes,
                    const float* __restrict__ Wt2, const float* __restrict__ bt2,
                    const float* __restrict__ Wv2, const float* __restrict__ bv2,
                    float* __restrict__ out_xtime)
{
    __shared__ float w2t[4096];
    __shared__ float red_a[256], red_b[256];
    __shared__ float stats2_s[128];
    __shared__ float xbar_s[64];

    int l = blockIdx.x;
    int tid = threadIdx.x;

    const float* W2 = (l < TB) ? Wt2 : Wv2;
    for (int i = tid; i < 4096; i += blockDim.x) {
        int o = i >> 6, d = i & 63;
        w2t[d*64 + o] = W2[i];
    }

    {
        int o = tid & 63, sl = tid >> 6;
        float s = 0.f, ss = 0.f;
        for (int ch = sl; ch < 320; ch += 4) {
            s  += g_part2[(ch*64 + o)*2 + 0];
            ss += g_part2[(ch*64 + o)*2 + 1];
        }
        red_a[tid] = s; red_b[tid] = ss;
        __syncthreads();
        if (tid < 64) {
            float S  = red_a[tid] + red_a[64+tid] + red_a[128+tid] + red_a[192+tid];
            float SS = red_b[tid] + red_b[64+tid] + red_b[128+tid] + red_b[192+tid];
            float cnt = 64.f * (float)LTOT;
            float m = S/cnt, v = SS/cnt - m*m;
            stats2_s[tid*2 + 0] = m;
            stats2_s[tid*2 + 1] = rsqrtf(v + EPSB);
        }
        __syncthreads();
    }

    {
        int d = tid & 63, ns = tid >> 6;
        float m = stats2_s[d*2], r = stats2_s[d*2+1];
        float g = gs[d], bb = bes[d];
        float acc = 0.f;
        for (int n = ns; n < 64; n += 4)
            acc += hswish(g * (g_xs[(n*64 + d)*LTOT + l] - m) * r + bb);
        red_a[tid] = acc;
        __syncthreads();
        if (tid < 64)
            xbar_s[tid] = (red_a[tid] + red_a[64+tid] + red_a[128+tid] + red_a[192+tid]) * (1.0f/64.0f);
        __syncthreads();
    }

    if (tid < 64) {
        int o = tid;
        float acc = (l < TB) ? bt2[o] : bv2[o];
        #pragma unroll 8
        for (int d = 0; d < 64; d++) acc += w2t[d*64 + o] * xbar_s[d];
        float sg = 1.0f / (1.0f + expf(-acc));
        if (l < TB) out_xtime[o*TB + l] = sg;
        else        g_scale[(l - TB)*64 + o] = tanhf(sg) + 1.0f;
    }
}

// ---------------- K7: GEMM + inline BN partials + shifted-layout fp16 store ----------------
// 800 threads = 25 warps, warp w (0..24), lane = ddg; 12t x 2dd per thread via FFMA2.
// a-loads: exactly 3x LDS.128 per c (12 t = 6 packed pairs). No idle warps.
#define XMP_CS 12
#define XMP_WS 772      // 64*12 + 4 pad
#define XMP_TOT (VB*XMP_WS)   // 19300 floats; also reused as 64x300 perm buffer (19200)
__global__ void __launch_bounds__(800, 1)
k7(const float* __restrict__ x0, const float* __restrict__ Lw,
   const float* __restrict__ Lb)
{
    extern __shared__ float sm7[];
    float* xmp = sm7;                 // 19300
    float* lws = sm7 + XMP_TOT;       // 4096, 16B-aligned
    float* ssc = lws + 4096;          // 25*65
    float* lbs = ssc + 1625;          // 64

    int b = blockIdx.x;
    int n = b / (TB/K7T);             // TB/K7T = 25
    int t0 = (b % (TB/K7T)) * K7T;
    int tid = threadIdx.x;

    for (int i = tid; i < 4096; i += 800) lws[i] = Lw[i];
    for (int i = tid; i < VB*CB; i += 800) {
        int w = i >> 6, c = i & 63;
        ssc[w*65 + c] = g_scale[i];
    }
    if (tid < 64) lbs[tid] = Lb[tid];
    __syncthreads();

    // build: exactly 2 (c,v) pairs per thread; strength-reduced t-loop (MLP 12)
    const float* xbase = x0 + ((size_t)(n*64) * 300 + t0) * 25;
    #pragma unroll
    for (int rep = 0; rep < 2; rep++) {
        int pr = rep*800 + tid;
        int c = pr / 25;
        int v = pr - c*25;
        int w = v - (c % 25); if (w < 0) w += 25;
        float sc = ssc[w*65 + c];
        const float* src = xbase + (size_t)c * 7500 + v;
        float* dst = xmp + w*XMP_WS + c*XMP_CS;
        #pragma unroll
        for (int t = 0; t < K7T; t++)
            dst[t] = src[t*25] * sc;
    }
    __syncthreads();

    int w   = tid >> 5;     // warp index == w, 0..24 (all warps active)
    int ddg = tid & 31;
    int dd0 = ddg << 1;
    unsigned long long acc[6][2];

    {
        const unsigned long long* xq = (const unsigned long long*)(xmp + w*XMP_WS);
        {
            unsigned long long i0 = pk2(lbs[dd0],     lbs[dd0]);
            unsigned long long i1 = pk2(lbs[dd0 + 1], lbs[dd0 + 1]);
            #pragma unroll
            for (int tp = 0; tp < 6; tp++) { acc[tp][0] = i0; acc[tp][1] = i1; }
        }
        #pragma unroll 4
        for (int c = 0; c < 64; c++) {
            ulonglong2 A01 = *(const ulonglong2*)(xq + c*6);      // (t0,t1),(t2,t3)
            ulonglong2 A23 = *(const ulonglong2*)(xq + c*6 + 2);  // (t4,t5),(t6,t7)
            ulonglong2 A45 = *(const ulonglong2*)(xq + c*6 + 4);  // (t8,t9),(t10,t11)
            float2 bf = *(const float2*)&lws[(c << 6) + dd0];
            unsigned long long b0 = pk2(bf.x, bf.x);
            unsigned long long b1 = pk2(bf.y, bf.y);
            fma2(acc[0][0], A01.x, b0); fma2(acc[0][1], A01.x, b1);
            fma2(acc[1][0], A01.y, b0); fma2(acc[1][1], A01.y, b1);
            fma2(acc[2][0], A23.x, b0); fma2(acc[2][1], A23.x, b1);
            fma2(acc[3][0], A23.y, b0); fma2(acc[3][1], A23.y, b1);
            fma2(acc[4][0], A45.x, b0); fma2(acc[4][1], A45.x, b1);
            fma2(acc[5][0], A45.y, b0); fma2(acc[5][1], A45.y, b1);
        }
    }
    __syncthreads();   // all xmp reads done; reuse as permute buffer

    float* ysm = sm7;  // [64][300]: dd*300 + t*25 + i
    {
        int i_e = (w + dd0) % 25;          // dest i for feature dd0
        int i_o = (w + dd0 + 1) % 25;      // dest i for feature dd0+1
        float* ysm_e = ysm + dd0*300 + i_e;
        float* ysm_o = ysm + (dd0 + 1)*300 + i_o;
        float psum0 = 0.f, psum1 = 0.f, psq0 = 0.f, psq1 = 0.f;
        #pragma unroll
        for (int tp = 0; tp < 6; tp++) {
            float e0, o0, e1, o1;
            upk2(e0, o0, acc[tp][0]);      // (t=2tp, dd0), (t=2tp+1, dd0)
            upk2(e1, o1, acc[tp][1]);      // (t=2tp, dd0+1), (t=2tp+1, dd0+1)
            ysm_e[(2*tp)*25]     = e0;
            ysm_o[(2*tp)*25]     = e1;
            ysm_e[(2*tp + 1)*25] = o0;
            ysm_o[(2*tp + 1)*25] = o1;
            psum0 += e0 + o0; psq0 += e0*e0 + o0*o0;
            psum1 += e1 + o1; psq1 += e1*e1 + o1*o1;
        }
        *(float2*)&g_part3[(size_t)b*3200 + (w << 6) + dd0]        = make_float2(psum0, psum1);
        *(float2*)&g_part3[(size_t)b*3200 + 1600 + (w << 6) + dd0] = make_float2(psq0,  psq1);
    }
    __syncthreads();

    // coalesced half2 store: g_y0h layout [n][dd][t][i]; per dd the 300 floats
    // are contiguous. 9600 half2 = 12 per thread exactly. All indices even -> 4B aligned.
    size_t base = (size_t)n * 480000 + (size_t)t0 * 25;
    #pragma unroll
    for (int k = 0; k < 12; k++) {
        int idx2 = k*800 + tid;            // pair index, 0..9599
        int dd = idx2 / 150;
        int r2 = idx2 - dd*150;
        float2 v = *(const float2*)&ysm[dd*300 + 2*r2];
        *(__half2*)&g_y0h[base + (size_t)dd*7500 + 2*r2] = __floats2half2_rn(v.x, v.y);
    }
}

// ---------------- K8b: reduce BN partials -> per-feature stats ----------------
__global__ void k8b()
{
    __shared__ float red_s[256], red_ss[256];
    int f = blockIdx.x * 32 + (threadIdx.x & 31);
    int sl = threadIdx.x >> 5;
    float s = 0.f, ss = 0.f;
    for (int b = sl; b < K7_BLOCKS; b += 8) {
        s  += g_part3[(size_t)b*3200 + f];
        ss += g_part3[(size_t)b*3200 + 1600 + f];
    }
    red_s[threadIdx.x] = s; red_ss[threadIdx.x] = ss;
    __syncthreads();
    if (threadIdx.x < 32) {
        float S = 0.f, SS = 0.f;
        #pragma unroll
        for (int k = 0; k < 8; k++) { S += red_s[k*32 + threadIdx.x]; SS += red_ss[k*32 + threadIdx.x]; }
        int ff = blockIdx.x * 32 + threadIdx.x;
        float cnt = (float)NTOT;
        float m = S/cnt, v = SS/cnt - m*m;
        g_stats3[ff*2 + 0] = m;
        g_stats3[ff*2 + 1] = rsqrtf(v + EPSB);
    }
}

// ---------------- K9: pure streaming BN + residual + relu (fp16 y0 input) ----------------
// g_y0h is already in output layout [n][dd][t][i]; block = one (n,dd) row (7500 elems).
__global__ void k9(const float* __restrict__ x0, const float* __restrict__ gbn,
                   const float* __restrict__ bbn, float* __restrict__ out)
{
    __shared__ float A[25], Bc[25];
    int b = blockIdx.x;            // n*64 + dd
    int dd = b & 63;
    int tid = threadIdx.x;

    if (tid < 25) {
        int i = tid;
        int wsrc = i - (dd % 25); if (wsrc < 0) wsrc += 25;   // pre-shift w for (i,dd)
        int p = wsrc*64 + dd;      // stats feature (pre-shift)
        int q = i*64 + dd;         // gbn/bbn feature (post-shift)
        float m = g_stats3[p*2], r = g_stats3[p*2 + 1];
        float g = gbn[q];
        A[i]  = g * r;
        Bc[i] = bbn[q] - g * r * m;
    }
    __syncthreads();

    const __half2* y2 = (const __half2*)(g_y0h + (size_t)b * 7500);  // b*7500 even
    const float4*  x4 = (const float4*)(x0    + (size_t)b * 7500);
    float4*        o4 = (float4*)(out         + (size_t)b * 7500);
    for (int p4 = tid; p4 < 1875; p4 += blockDim.x) {
        float2 ya = __half22float2(y2[2*p4]);
        float2 yb = __half22float2(y2[2*p4 + 1]);
        float4 x = x4[p4];
        int i = (p4 << 2) % 25;
        float4 o;
        o.x = fmaxf(fmaf(A[i], ya.x, Bc[i]) + x.x, 0.f); if (++i == 25) i = 0;
        o.y = fmaxf(fmaf(A[i], ya.y, Bc[i]) + x.y, 0.f); if (++i == 25) i = 0;
        o.z = fmaxf(fmaf(A[i], yb.x, Bc[i]) + x.z, 0.f); if (++i == 25) i = 0;
        o.w = fmaxf(fmaf(A[i], yb.y, Bc[i]) + x.w, 0.f);
        o4[p4] = o;
    }
}

// ---------------- launcher (6 launches; slot 4 = k7 for ncu capture) ----------------
extern "C" void kernel_launch(void* const* d_in, const int* in_sizes, int n_in,
                              void* d_out, int out_size)
{
    const float* x0  = (const float*)d_in[0];
    const float* Wv  = (const float*)d_in[3];
    const float* bv  = (const float*)d_in[4];
    const float* gv  = (const float*)d_in[5];
    const float* bev = (const float*)d_in[6];
    const float* Wt  = (const float*)d_in[7];
    const float* bt  = (const float*)d_in[8];
    const float* gt  = (const float*)d_in[9];
    const float* bet = (const float*)d_in[10];
    const float* Ws  = (const float*)d_in[11];
    const float* bs  = (const float*)d_in[12];
    const float* gs  = (const float*)d_in[13];
    const float* bes = (const float*)d_in[14];
    const float* Wv2 = (const float*)d_in[15];
    const float* bv2 = (const float*)d_in[16];
    const float* Wt2 = (const float*)d_in[17];
    const float* bt2 = (const float*)d_in[18];
    const float* Lw  = (const float*)d_in[19];
    const float* Lb  = (const float*)d_in[20];
    const float* gbn = (const float*)d_in[21];
    const float* bbn = (const float*)d_in[22];
    float* out = (float*)d_out;

    static_assert((TB % K7T) == 0, "k7 t tiling");
    static_assert((XMP_TOT % 4) == 0, "xmp align");
    static_assert(XMP_CS * CB < XMP_WS, "xmp pad");
    static_assert(DB * 300 <= XMP_TOT, "perm buffer fits");
    static_assert(CB*VB == 2*800, "build pairs = 2/thread");

    const int smem3 = (64*68 + 4096 + 17*64*2) * 4;                 // 51200
    const int smem7 = (XMP_TOT + 4096 + 1625 + 64) * 4;             // 100340
    cudaFuncSetAttribute(k3, cudaFuncAttributeMaxDynamicSharedMemorySize, smem3);
    cudaFuncSetAttribute(k7, cudaFuncAttributeMaxDynamicSharedMemorySize, smem7);

    k1 <<<NB*CB, 256>>>(x0, Wv, bv, Wt, bt);
    k3 <<<NB*5, 288, smem3>>>(gv, bev, gt, bet, Ws, bs);
    k56<<<LTOT, 256>>>(gs, bes, Wt2, bt2, Wv2, bv2, out + Y_SIZE);
    k7 <<<K7_BLOCKS, 800, smem7>>>(x0, Lw, Lb);
    k8b<<<FEAT/32, 256>>>();
    k9 <<<NB*DB, 256>>>(x0, gbn, bbn, out);
}